// round 1
// baseline (speedup 1.0000x reference)
#include <cuda_runtime.h>

// Problem constants
#define B_  8
#define N_  1024
#define C_  64
#define O_  64
#define KM  4          // K+1
#define BN  (B_*N_)    // 8192

// -------- device scratch (no allocations allowed) --------
__device__ float g_sRi[BN], g_sIi[BN], g_sRj[BN], g_sIj[BN];
__device__ float g_rsum[BN];                 // 1 / sum_i exp(mag[b,i,j]) per (b,j)
__device__ float g_rowR[KM*BN], g_rowI[KM*BN];  // (b*4+m)*N + i

// ============================================================
// Kernel 1: per-(b,n) attention projections. One warp per (b,n).
//   sRi = X_r . Wr[:C] - X_i . Wi[:C]   (+ bias_r folded in)
//   sIi = X_r . Wi[:C] + X_i . Wr[:C]   (+ bias_i folded in)
//   sRj/sIj use the second half of the attention weights.
// ============================================================
__global__ void __launch_bounds__(256) k1_proj(
    const float* __restrict__ Xr, const float* __restrict__ Xi,
    const float* __restrict__ awr, const float* __restrict__ awi,
    const float* __restrict__ abr, const float* __restrict__ abi)
{
    int warp = (blockIdx.x * blockDim.x + threadIdx.x) >> 5;
    int lane = threadIdx.x & 31;
    if (warp >= BN) return;
    const float* xr = Xr + warp * C_;
    const float* xi = Xi + warp * C_;
    float sRi = 0.f, sIi = 0.f, sRj = 0.f, sIj = 0.f;
#pragma unroll
    for (int t = 0; t < 2; t++) {
        int c = lane + t * 32;
        float a = xr[c], b = xi[c];
        float wri = awr[c],      wii = awi[c];
        float wrj = awr[C_ + c], wij = awi[C_ + c];
        sRi += a * wri - b * wii;
        sIi += a * wii + b * wri;
        sRj += a * wrj - b * wij;
        sIj += a * wij + b * wrj;
    }
#pragma unroll
    for (int off = 16; off; off >>= 1) {
        sRi += __shfl_xor_sync(0xffffffffu, sRi, off);
        sIi += __shfl_xor_sync(0xffffffffu, sIi, off);
        sRj += __shfl_xor_sync(0xffffffffu, sRj, off);
        sIj += __shfl_xor_sync(0xffffffffu, sIj, off);
    }
    if (lane == 0) {
        g_sRi[warp] = sRi + abr[0];
        g_sIi[warp] = sIi + abi[0];
        g_sRj[warp] = sRj;
        g_sIj[warp] = sIj;
    }
}

// ============================================================
// Kernel 2: softmax denominator per (b,j): sum over i of exp(mag).
// mag is bounded (<~8) so no max-subtraction needed (identical math).
// Stores the reciprocal so the main kernel multiplies instead of divides.
// ============================================================
__global__ void __launch_bounds__(128) k2_sumexp(
    const float* __restrict__ par, const float* __restrict__ pai)
{
    int bj = blockIdx.x;          // b*N + j
    int b  = bj >> 10;
    float sRj = g_sRj[bj], sIj = g_sIj[bj];
    float a_r = par[0], a_i = pai[0];
    const float* sRi = g_sRi + (b << 10);
    const float* sIi = g_sIi + (b << 10);
    float acc = 0.f;
#pragma unroll
    for (int t = 0; t < N_ / 128; t++) {
        int i = threadIdx.x + t * 128;
        float sr = sRi[i] + sRj;
        float si = sIi[i] + sIj;
        float pr = sr >= 0.f ? sr : a_r * sr;
        float pi = si >= 0.f ? si : a_i * si;
        float r2 = pr * pr + pi * pi;
        float inv = rsqrtf(fmaxf(r2, 1e-30f));
        float mag = r2 * inv;
        acc += __expf(mag);
    }
    __shared__ float sred[4];
#pragma unroll
    for (int off = 16; off; off >>= 1) acc += __shfl_xor_sync(0xffffffffu, acc, off);
    if ((threadIdx.x & 31) == 0) sred[threadIdx.x >> 5] = acc;
    __syncthreads();
    if (threadIdx.x == 0) {
        float t = sred[0] + sred[1] + sred[2] + sred[3];
        g_rsum[bj] = 1.f / t;
    }
}

// ============================================================
// Kernel 3 (dominant, HBM-bound): one block per (b,i) row.
// Recomputes ar/ai on the fly, streams L_real/L_imag for all 4 m,
// reduces over j -> rowR[b,m,i], rowI[b,m,i].
// ============================================================
__global__ void __launch_bounds__(256) k3_main(
    const float* __restrict__ Lr, const float* __restrict__ Li,
    const float* __restrict__ par, const float* __restrict__ pai)
{
    int bi = blockIdx.x;          // b*N + i
    int b  = bi >> 10;
    int i  = bi & 1023;
    int tid = threadIdx.x;
    int j0 = tid * 4;

    float sRi = g_sRi[bi], sIi = g_sIi[bi];
    float a_r = par[0], a_i = pai[0];

    const int bj0 = (b << 10) + j0;
    float4 sRj4 = *(const float4*)(g_sRj + bj0);
    float4 sIj4 = *(const float4*)(g_sIj + bj0);
    float4 rs4  = *(const float4*)(g_rsum + bj0);
    float sRjv[4] = {sRj4.x, sRj4.y, sRj4.z, sRj4.w};
    float sIjv[4] = {sIj4.x, sIj4.y, sIj4.z, sIj4.w};
    float rsv [4] = {rs4.x,  rs4.y,  rs4.z,  rs4.w };

    float ar[4], ai[4];
#pragma unroll
    for (int k = 0; k < 4; k++) {
        float sr = sRi + sRjv[k];
        float si = sIi + sIjv[k];
        float pr = sr >= 0.f ? sr : a_r * sr;
        float pi = si >= 0.f ? si : a_i * si;
        float r2 = pr * pr + pi * pi;
        float inv = rsqrtf(fmaxf(r2, 1e-30f));
        float mag = r2 * inv;
        float e = __expf(mag);
        float sc = e * inv * rsv[k];
        ar[k] = sc * pr;
        ai[k] = sc * pi;
    }

    float accR[4], accI[4];
#pragma unroll
    for (int m = 0; m < 4; m++) { accR[m] = 0.f; accI[m] = 0.f; }

#pragma unroll
    for (int m = 0; m < 4; m++) {
        size_t base = ((size_t)((b * 4 + m) * N_ + i)) * N_ + j0;
        float4 lr = *(const float4*)(Lr + base);
        float4 li = *(const float4*)(Li + base);
        accR[m] += lr.x * ar[0] - li.x * ai[0];
        accR[m] += lr.y * ar[1] - li.y * ai[1];
        accR[m] += lr.z * ar[2] - li.z * ai[2];
        accR[m] += lr.w * ar[3] - li.w * ai[3];
        accI[m] += lr.x * ai[0] + li.x * ar[0];
        accI[m] += lr.y * ai[1] + li.y * ar[1];
        accI[m] += lr.z * ai[2] + li.z * ar[2];
        accI[m] += lr.w * ai[3] + li.w * ar[3];
    }

    // block reduction of 8 values
    __shared__ float sred[8][8];   // [warp][q]
#pragma unroll
    for (int q = 0; q < 8; q++) {
        float x = (q < 4) ? accR[q] : accI[q - 4];
#pragma unroll
        for (int off = 16; off; off >>= 1) x += __shfl_xor_sync(0xffffffffu, x, off);
        if ((tid & 31) == 0) sred[tid >> 5][q] = x;
    }
    __syncthreads();
    if (tid < 8) {
        float x = 0.f;
#pragma unroll
        for (int w = 0; w < 8; w++) x += sred[w][tid];
        int m = tid & 3;
        if (tid < 4) g_rowR[(b * 4 + m) * N_ + i] = x;
        else         g_rowI[(b * 4 + m) * N_ + i] = x;
    }
}

// ============================================================
// Kernel 4: final einsums.
//   PR[m,o] = sum_c Xr[b,j,c] wr[m,c,o];  PI[m,o] = sum_c Xi[b,j,c] wi[m,c,o]
//   real[b,j,o] = sum_m rowR*PR - rowI*PI
//   imag[b,j,o] = sum_m rowI*PR + rowR*PI
// Thread = (og in 0..15 -> 4 o via float4, jl in 0..15). Block does 64 j
// in 4 passes so the 131 KB of w stays L1-resident.
// ============================================================
__global__ void __launch_bounds__(256) k4_out(
    const float* __restrict__ Xr, const float* __restrict__ Xi,
    const float4* __restrict__ wr4, const float4* __restrict__ wi4,
    float* __restrict__ out)
{
    __shared__ float Xr_s[16 * 65];
    __shared__ float Xi_s[16 * 65];
    __shared__ float rR_s[16][4];
    __shared__ float rI_s[16][4];

    int tid = threadIdx.x;
    int og = tid & 15;
    int jl = tid >> 4;
    int jblock = blockIdx.x * 64;   // 64 consecutive (b*N+j), same b

    for (int p = 0; p < 4; p++) {
        int jbase = jblock + p * 16;
        // cooperative X load (coalesced)
#pragma unroll
        for (int r = 0; r < 4; r++) {
            int u = r * 256 + tid;
            int pi = u >> 6, c = u & 63;
            Xr_s[pi * 65 + c] = Xr[jbase * C_ + u];
            Xi_s[pi * 65 + c] = Xi[jbase * C_ + u];
        }
        if (tid < 128) {
            int half = tid >> 6;
            int t = tid & 63;
            int pi = t >> 2, m = t & 3;
            int jj = jbase + pi;
            int b = jj >> 10, j = jj & 1023;
            if (half == 0) rR_s[pi][m] = g_rowR[(b * 4 + m) * N_ + j];
            else           rI_s[pi][m] = g_rowI[(b * 4 + m) * N_ + j];
        }
        __syncthreads();

        float4 PR[4], PI[4];
#pragma unroll
        for (int m = 0; m < 4; m++) {
            PR[m] = make_float4(0.f, 0.f, 0.f, 0.f);
            PI[m] = make_float4(0.f, 0.f, 0.f, 0.f);
        }
#pragma unroll 4
        for (int c = 0; c < C_; c++) {
            float xr = Xr_s[jl * 65 + c];
            float xi = Xi_s[jl * 65 + c];
#pragma unroll
            for (int m = 0; m < 4; m++) {
                float4 wr = wr4[(m * C_ + c) * 16 + og];
                float4 wi = wi4[(m * C_ + c) * 16 + og];
                PR[m].x += xr * wr.x; PR[m].y += xr * wr.y;
                PR[m].z += xr * wr.z; PR[m].w += xr * wr.w;
                PI[m].x += xi * wi.x; PI[m].y += xi * wi.y;
                PI[m].z += xi * wi.z; PI[m].w += xi * wi.w;
            }
        }

        float4 re = make_float4(0.f, 0.f, 0.f, 0.f);
        float4 im = make_float4(0.f, 0.f, 0.f, 0.f);
#pragma unroll
        for (int m = 0; m < 4; m++) {
            float a = rR_s[jl][m];
            float bI = rI_s[jl][m];
            re.x += a * PR[m].x - bI * PI[m].x;
            re.y += a * PR[m].y - bI * PI[m].y;
            re.z += a * PR[m].z - bI * PI[m].z;
            re.w += a * PR[m].w - bI * PI[m].w;
            im.x += bI * PR[m].x + a * PI[m].x;
            im.y += bI * PR[m].y + a * PI[m].y;
            im.z += bI * PR[m].z + a * PI[m].z;
            im.w += bI * PR[m].w + a * PI[m].w;
        }
        int jj = jbase + jl;
        ((float4*)out)[jj * 16 + og] = re;                        // real
        ((float4*)out)[(BN * O_ / 4) + jj * 16 + og] = im;        // imag
        __syncthreads();
    }
}

// ============================================================
extern "C" void kernel_launch(void* const* d_in, const int* in_sizes, int n_in,
                              void* d_out, int out_size)
{
    const float* Xr  = (const float*)d_in[0];
    const float* Xi  = (const float*)d_in[1];
    const float* Lr  = (const float*)d_in[2];
    const float* Li  = (const float*)d_in[3];
    const float* wr  = (const float*)d_in[4];
    const float* wi  = (const float*)d_in[5];
    const float* awr = (const float*)d_in[6];
    const float* awi = (const float*)d_in[7];
    const float* abr = (const float*)d_in[8];
    const float* abi = (const float*)d_in[9];
    const float* par = (const float*)d_in[10];
    const float* pai = (const float*)d_in[11];
    float* out = (float*)d_out;

    k1_proj  <<<BN / 8, 256>>>(Xr, Xi, awr, awi, abr, abi);
    k2_sumexp<<<BN,     128>>>(par, pai);
    k3_main  <<<BN,     256>>>(Lr, Li, par, pai);
    k4_out   <<<BN / 64, 256>>>(Xr, Xi, (const float4*)wr, (const float4*)wi, out);
}

// round 4
// speedup vs baseline: 1.9518x; 1.9518x over previous
#include <cuda_runtime.h>

// Problem constants
#define B_  8
#define N_  1024
#define C_  64
#define O_  64
#define KM  4          // K+1
#define BN  (B_*N_)    // 8192

// -------- device scratch (no allocations allowed) --------
__device__ float g_sRi[BN], g_sIi[BN], g_sRj[BN], g_sIj[BN];
__device__ float g_rsum[BN];                 // 1 / sum_i exp(mag[b,i,j]) per (b,j)
__device__ float g_rowR[KM*BN], g_rowI[KM*BN];  // (b*4+m)*N + i

// ============================================================
// Kernel 1: per-(b,n) attention projections. One warp per (b,n).
// ============================================================
__global__ void __launch_bounds__(256) k1_proj(
    const float* __restrict__ Xr, const float* __restrict__ Xi,
    const float* __restrict__ awr, const float* __restrict__ awi,
    const float* __restrict__ abr, const float* __restrict__ abi)
{
    int warp = (blockIdx.x * blockDim.x + threadIdx.x) >> 5;
    int lane = threadIdx.x & 31;
    if (warp >= BN) return;
    const float* xr = Xr + warp * C_;
    const float* xi = Xi + warp * C_;
    float sRi = 0.f, sIi = 0.f, sRj = 0.f, sIj = 0.f;
#pragma unroll
    for (int t = 0; t < 2; t++) {
        int c = lane + t * 32;
        float a = xr[c], b = xi[c];
        float wri = awr[c],      wii = awi[c];
        float wrj = awr[C_ + c], wij = awi[C_ + c];
        sRi += a * wri - b * wii;
        sIi += a * wii + b * wri;
        sRj += a * wrj - b * wij;
        sIj += a * wij + b * wrj;
    }
#pragma unroll
    for (int off = 16; off; off >>= 1) {
        sRi += __shfl_xor_sync(0xffffffffu, sRi, off);
        sIi += __shfl_xor_sync(0xffffffffu, sIi, off);
        sRj += __shfl_xor_sync(0xffffffffu, sRj, off);
        sIj += __shfl_xor_sync(0xffffffffu, sIj, off);
    }
    if (lane == 0) {
        g_sRi[warp] = sRi + abr[0];
        g_sIi[warp] = sIi + abi[0];
        g_sRj[warp] = sRj;
        g_sIj[warp] = sIj;
    }
}

// ============================================================
// Kernel 2: softmax denominator per (b,j): sum over i of exp(mag).
// mag is bounded (<~8) so no max-subtraction needed (identical math).
// ============================================================
__global__ void __launch_bounds__(128) k2_sumexp(
    const float* __restrict__ par, const float* __restrict__ pai)
{
    int bj = blockIdx.x;          // b*N + j
    int b  = bj >> 10;
    float sRj = g_sRj[bj], sIj = g_sIj[bj];
    float a_r = par[0], a_i = pai[0];
    const float* sRi = g_sRi + (b << 10);
    const float* sIi = g_sIi + (b << 10);
    float acc = 0.f;
#pragma unroll
    for (int t = 0; t < N_ / 128; t++) {
        int i = threadIdx.x + t * 128;
        float sr = sRi[i] + sRj;
        float si = sIi[i] + sIj;
        float pr = sr >= 0.f ? sr : a_r * sr;
        float pi = si >= 0.f ? si : a_i * si;
        float r2 = pr * pr + pi * pi;
        float inv = rsqrtf(fmaxf(r2, 1e-30f));
        float mag = r2 * inv;
        acc += __expf(mag);
    }
    __shared__ float sred[4];
#pragma unroll
    for (int off = 16; off; off >>= 1) acc += __shfl_xor_sync(0xffffffffu, acc, off);
    if ((threadIdx.x & 31) == 0) sred[threadIdx.x >> 5] = acc;
    __syncthreads();
    if (threadIdx.x == 0) {
        float t = sred[0] + sred[1] + sred[2] + sred[3];
        g_rsum[bj] = 1.f / t;
    }
}

// ============================================================
// Kernel 3 (dominant, HBM-bound): one block per (b,i) row.
// Streams L_real/L_imag exactly once (268 MB) -> rowR/rowI.
// ============================================================
__global__ void __launch_bounds__(256) k3_main(
    const float* __restrict__ Lr, const float* __restrict__ Li,
    const float* __restrict__ par, const float* __restrict__ pai)
{
    int bi = blockIdx.x;          // b*N + i
    int b  = bi >> 10;
    int i  = bi & 1023;
    int tid = threadIdx.x;
    int j0 = tid * 4;

    float sRi = g_sRi[bi], sIi = g_sIi[bi];
    float a_r = par[0], a_i = pai[0];

    const int bj0 = (b << 10) + j0;
    float4 sRj4 = *(const float4*)(g_sRj + bj0);
    float4 sIj4 = *(const float4*)(g_sIj + bj0);
    float4 rs4  = *(const float4*)(g_rsum + bj0);
    float sRjv[4] = {sRj4.x, sRj4.y, sRj4.z, sRj4.w};
    float sIjv[4] = {sIj4.x, sIj4.y, sIj4.z, sIj4.w};
    float rsv [4] = {rs4.x,  rs4.y,  rs4.z,  rs4.w };

    float ar[4], ai[4];
#pragma unroll
    for (int k = 0; k < 4; k++) {
        float sr = sRi + sRjv[k];
        float si = sIi + sIjv[k];
        float pr = sr >= 0.f ? sr : a_r * sr;
        float pi = si >= 0.f ? si : a_i * si;
        float r2 = pr * pr + pi * pi;
        float inv = rsqrtf(fmaxf(r2, 1e-30f));
        float mag = r2 * inv;
        float e = __expf(mag);
        float sc = e * inv * rsv[k];
        ar[k] = sc * pr;
        ai[k] = sc * pi;
    }

    float accR[4], accI[4];
#pragma unroll
    for (int m = 0; m < 4; m++) { accR[m] = 0.f; accI[m] = 0.f; }

#pragma unroll
    for (int m = 0; m < 4; m++) {
        size_t base = ((size_t)((b * 4 + m) * N_ + i)) * N_ + j0;
        float4 lr = *(const float4*)(Lr + base);
        float4 li = *(const float4*)(Li + base);
        accR[m] += lr.x * ar[0] - li.x * ai[0];
        accR[m] += lr.y * ar[1] - li.y * ai[1];
        accR[m] += lr.z * ar[2] - li.z * ai[2];
        accR[m] += lr.w * ar[3] - li.w * ai[3];
        accI[m] += lr.x * ai[0] + li.x * ar[0];
        accI[m] += lr.y * ai[1] + li.y * ar[1];
        accI[m] += lr.z * ai[2] + li.z * ar[2];
        accI[m] += lr.w * ai[3] + li.w * ar[3];
    }

    __shared__ float sred[8][8];   // [warp][q]
#pragma unroll
    for (int q = 0; q < 8; q++) {
        float x = (q < 4) ? accR[q] : accI[q - 4];
#pragma unroll
        for (int off = 16; off; off >>= 1) x += __shfl_xor_sync(0xffffffffu, x, off);
        if ((tid & 31) == 0) sred[tid >> 5][q] = x;
    }
    __syncthreads();
    if (tid < 8) {
        float x = 0.f;
#pragma unroll
        for (int w = 0; w < 8; w++) x += sred[w][tid];
        int m = tid & 3;
        if (tid < 4) g_rowR[(b * 4 + m) * N_ + i] = x;
        else         g_rowI[(b * 4 + m) * N_ + i] = x;
    }
}

// ============================================================
// Kernel 4: final einsums. 48KB STATIC smem (no attribute calls).
// Block = 64 threads = (og 0..3 [float4 over o], jl 0..15), handles
// o-slice oq (16 o) and a 32-j tile (2 j per thread).
//   smem: w slice (4m x 64c x 16o x r/i) = 32KB
//         X tile  (32j x 64c x r/i, XOR-swizzled) = 16KB
// Grid = 4 oq x 256 j-groups = 1024 blocks, 4 blocks/SM concurrent.
// ============================================================
#define FMA4(acc, s, v) \
    acc.x += (s) * (v).x; acc.y += (s) * (v).y; \
    acc.z += (s) * (v).z; acc.w += (s) * (v).w;

__global__ void __launch_bounds__(64) k4_out(
    const float* __restrict__ Xr, const float* __restrict__ Xi,
    const float4* __restrict__ wr4, const float4* __restrict__ wi4,
    float* __restrict__ out)
{
    __shared__ float4 wr_s[KM * C_ * 4];    // 1024 f4 = 16 KB
    __shared__ float4 wi_s[KM * C_ * 4];    // 16 KB
    __shared__ float4 x_s[2][512];          // [ri][j*16 + (cq ^ (j&15))] = 16 KB
    // total = 49152 B = 48 KB exactly

    int tid = threadIdx.x;
    int og  = tid & 3;
    int jl  = tid >> 2;                     // 0..15
    int bx  = blockIdx.x;
    int jg  = bx & 255;
    int oq  = bx >> 8;
    int jbase = jg * 32;                    // global (b*N+j) base, same b within tile
    int b   = jbase >> 10;

    // ---- load w slice (coalesced 64B runs, from L2) ----
#pragma unroll
    for (int r = 0; r < 16; r++) {
        int e  = r * 64 + tid;              // 0..1023
        int mc = e >> 2, o2 = e & 3;
        wr_s[e] = wr4[mc * 16 + oq * 4 + o2];
        wi_s[e] = wi4[mc * 16 + oq * 4 + o2];
    }
    // ---- load X tile (fully coalesced), XOR-swizzled store ----
    {
        const float4* XrG = (const float4*)(Xr + (size_t)jbase * C_);
        const float4* XiG = (const float4*)(Xi + (size_t)jbase * C_);
#pragma unroll
        for (int r = 0; r < 8; r++) {
            int e  = r * 64 + tid;          // 0..511
            int j  = e >> 4, cq = e & 15;
            int si = (j << 4) | (cq ^ (j & 15));
            x_s[0][si] = XrG[e];
            x_s[1][si] = XiG[e];
        }
    }
    __syncthreads();

    // ---- main accumulation ----
    float4 PR0[4], PI0[4], PR1[4], PI1[4];
#pragma unroll
    for (int m = 0; m < 4; m++) {
        PR0[m] = make_float4(0.f,0.f,0.f,0.f); PI0[m] = make_float4(0.f,0.f,0.f,0.f);
        PR1[m] = make_float4(0.f,0.f,0.f,0.f); PI1[m] = make_float4(0.f,0.f,0.f,0.f);
    }
    int j0 = jl, j1 = jl + 16;

#pragma unroll
    for (int cq = 0; cq < 16; cq++) {
        float4 xr0 = x_s[0][(j0 << 4) | (cq ^ j0)];
        float4 xi0 = x_s[1][(j0 << 4) | (cq ^ j0)];
        float4 xr1 = x_s[0][(j1 << 4) | (cq ^ jl)];   // j1 & 15 == jl
        float4 xi1 = x_s[1][(j1 << 4) | (cq ^ jl)];
        const float* fxr0 = (const float*)&xr0;
        const float* fxi0 = (const float*)&xi0;
        const float* fxr1 = (const float*)&xr1;
        const float* fxi1 = (const float*)&xi1;
#pragma unroll
        for (int ci = 0; ci < 4; ci++) {
            int c = cq * 4 + ci;
            float a0 = fxr0[ci], b0 = fxi0[ci];
            float a1 = fxr1[ci], b1 = fxi1[ci];
#pragma unroll
            for (int m = 0; m < 4; m++) {
                float4 wr = wr_s[((m << 6) + c) * 4 + og];
                float4 wi = wi_s[((m << 6) + c) * 4 + og];
                FMA4(PR0[m], a0, wr);
                FMA4(PI0[m], b0, wi);
                FMA4(PR1[m], a1, wr);
                FMA4(PI1[m], b1, wi);
            }
        }
    }

    // ---- combine over m with row vectors (L1/L2 hits) and store ----
#pragma unroll
    for (int jt = 0; jt < 2; jt++) {
        int jj = jbase + jl + jt * 16;      // global bn index
        int j  = jj & 1023;
        float4 re = make_float4(0.f,0.f,0.f,0.f);
        float4 im = make_float4(0.f,0.f,0.f,0.f);
#pragma unroll
        for (int m = 0; m < 4; m++) {
            float a  = g_rowR[(b * 4 + m) * N_ + j];
            float bi = g_rowI[(b * 4 + m) * N_ + j];
            float4 pr = jt ? PR1[m] : PR0[m];
            float4 pi = jt ? PI1[m] : PI0[m];
            re.x += a * pr.x - bi * pi.x;  re.y += a * pr.y - bi * pi.y;
            re.z += a * pr.z - bi * pi.z;  re.w += a * pr.w - bi * pi.w;
            im.x += bi * pr.x + a * pi.x;  im.y += bi * pr.y + a * pi.y;
            im.z += bi * pr.z + a * pi.z;  im.w += bi * pr.w + a * pi.w;
        }
        ((float4*)out)[jj * 16 + oq * 4 + og] = re;                 // real
        ((float4*)out)[BN * 16 + jj * 16 + oq * 4 + og] = im;       // imag
    }
}

// ============================================================
extern "C" void kernel_launch(void* const* d_in, const int* in_sizes, int n_in,
                              void* d_out, int out_size)
{
    const float* Xr  = (const float*)d_in[0];
    const float* Xi  = (const float*)d_in[1];
    const float* Lr  = (const float*)d_in[2];
    const float* Li  = (const float*)d_in[3];
    const float* wr  = (const float*)d_in[4];
    const float* wi  = (const float*)d_in[5];
    const float* awr = (const float*)d_in[6];
    const float* awi = (const float*)d_in[7];
    const float* abr = (const float*)d_in[8];
    const float* abi = (const float*)d_in[9];
    const float* par = (const float*)d_in[10];
    const float* pai = (const float*)d_in[11];
    float* out = (float*)d_out;

    k1_proj  <<<BN / 8, 256>>>(Xr, Xi, awr, awi, abr, abi);
    k2_sumexp<<<BN,     128>>>(par, pai);
    k3_main  <<<BN,     256>>>(Lr, Li, par, pai);
    k4_out   <<<4 * 256, 64>>>(Xr, Xi, (const float4*)wr, (const float4*)wi, out);
}